// round 1
// baseline (speedup 1.0000x reference)
#include <cuda_runtime.h>
#include <cuda_bf16.h>

// EdgeAwareLoss: fused Sobel-edge-magnitude L1 loss.
// pred, target: [4,1,128,256,256] fp32 -> scalar fp32 mean(|mag_p - mag_t|).
// 512 independent 256x256 slices, zero-padded SAME 3x3 Sobel.

#define HW 256
#define TS 32            // output tile side
#define TILE_W 34        // TS + 2 halo
#define SMEM_W 36        // padded row stride
#define NSLICES 512
#define N_TOTAL 33554432.0  // 4*1*128*256*256

__device__ double g_accum;

__global__ void ea_zero_kernel() { g_accum = 0.0; }

__global__ __launch_bounds__(256) void ea_edge_loss_kernel(
    const float* __restrict__ pred, const float* __restrict__ targ)
{
    __shared__ float sp[TILE_W * SMEM_W];
    __shared__ float st[TILE_W * SMEM_W];

    const int slice = blockIdx.z;                      // b*D + d, 0..511
    const long long base = (long long)slice * (HW * HW);
    const int gx0 = blockIdx.x * TS;
    const int gy0 = blockIdx.y * TS;
    const int tx  = threadIdx.x;                       // 0..31
    const int ty  = threadIdx.y;                       // 0..7
    const int tid = ty * 32 + tx;

    // Cooperative load of 34x34 halo tile for both inputs (zero padding OOB).
    #pragma unroll
    for (int idx = tid; idx < TILE_W * TILE_W; idx += 256) {
        const int r  = idx / TILE_W;
        const int c  = idx - r * TILE_W;
        const int gy = gy0 - 1 + r;
        const int gx = gx0 - 1 + c;
        float p = 0.0f, t = 0.0f;
        if (gy >= 0 && gy < HW && gx >= 0 && gx < HW) {
            const long long off = base + (long long)gy * HW + gx;
            p = __ldg(pred + off);
            t = __ldg(targ + off);
        }
        sp[r * SMEM_W + c] = p;
        st[r * SMEM_W + c] = t;
    }
    __syncthreads();

    float sum = 0.0f;
    #pragma unroll
    for (int ry = 0; ry < 4; ry++) {
        const int y = ty + ry * 8;                     // 0..31 tile row
        const float* p0 = sp + y * SMEM_W + tx;
        const float* p1 = p0 + SMEM_W;
        const float* p2 = p1 + SMEM_W;
        const float* q0 = st + y * SMEM_W + tx;
        const float* q1 = q0 + SMEM_W;
        const float* q2 = q1 + SMEM_W;

        // Cross-correlation with Sobel kernels (jax conv = no flip).
        float exp_ = (p0[2] - p0[0]) + 2.0f * (p1[2] - p1[0]) + (p2[2] - p2[0]);
        float eyp_ = (p2[0] + 2.0f * p2[1] + p2[2]) - (p0[0] + 2.0f * p0[1] + p0[2]);
        float ext_ = (q0[2] - q0[0]) + 2.0f * (q1[2] - q1[0]) + (q2[2] - q2[0]);
        float eyt_ = (q2[0] + 2.0f * q2[1] + q2[2]) - (q0[0] + 2.0f * q0[1] + q0[2]);

        const float mp = sqrtf(fmaf(exp_, exp_, fmaf(eyp_, eyp_, 1e-8f)));
        const float mt = sqrtf(fmaf(ext_, ext_, fmaf(eyt_, eyt_, 1e-8f)));
        sum += fabsf(mp - mt);
    }

    // Warp reduce
    #pragma unroll
    for (int o = 16; o > 0; o >>= 1)
        sum += __shfl_xor_sync(0xffffffffu, sum, o);

    __shared__ float wsum[8];
    if (tx == 0) wsum[ty] = sum;
    __syncthreads();

    if (tid < 8) {
        float s = wsum[tid];
        #pragma unroll
        for (int o = 4; o > 0; o >>= 1)
            s += __shfl_xor_sync(0xffu, s, o);
        if (tid == 0) atomicAdd(&g_accum, (double)s);
    }
}

__global__ void ea_finalize_kernel(float* __restrict__ out) {
    out[0] = (float)(g_accum / N_TOTAL);
}

extern "C" void kernel_launch(void* const* d_in, const int* in_sizes, int n_in,
                              void* d_out, int out_size) {
    const float* pred = (const float*)d_in[0];
    const float* targ = (const float*)d_in[1];
    float* out = (float*)d_out;

    ea_zero_kernel<<<1, 1>>>();

    dim3 grid(HW / TS, HW / TS, NSLICES);   // 8 x 8 x 512 = 32768 blocks
    dim3 blk(32, 8);
    ea_edge_loss_kernel<<<grid, blk>>>(pred, targ);

    ea_finalize_kernel<<<1, 1>>>(out);
}

// round 3
// speedup vs baseline: 1.7614x; 1.7614x over previous
#include <cuda_runtime.h>
#include <cuda_bf16.h>

// EdgeAwareLoss: fused Sobel-edge-magnitude L1 loss, single kernel.
// pred, target: [4,1,128,256,256] fp32 -> scalar fp32 mean(|mag_p - mag_t|).
// 512 slices of 256x256, zero-padded SAME 3x3 Sobel (XLA conv = cross-correlation).
//
// Separable form: per row, a[x] = v[x+1]-v[x-1], b[x] = v[x-1]+2v[x]+v[x+1].
// Then ex(y) = a(y-1)+2a(y)+a(y+1), ey(y) = b(y+1)-b(y-1).

#define HW       256
#define RB        16                 // output rows per block (band)
#define ROWS      18                 // RB + 2 halo rows
#define STRIDE   264                 // smem row stride (floats); data at cols [1..256]
#define NBANDS   (HW / RB)           // 16
#define NSLICES  512
#define NBLOCKS  (NSLICES * NBANDS)  // 8192
#define N_TOTAL  33554432.0          // 4*1*128*256*256

__device__ double       g_accum = 0.0;
__device__ unsigned int g_count = 0u;

__device__ __forceinline__ void horiz(const float* q, float& a, float& b) {
    // q points at center element (col x) of a shared row.
    const float l = q[-1], c = q[0], r = q[1];
    a = r - l;
    b = fmaf(2.0f, c, l + r);
}

__global__ __launch_bounds__(256) void ea_kernel(
    const float* __restrict__ pred, const float* __restrict__ targ,
    float* __restrict__ out)
{
    __shared__ float sp[ROWS * STRIDE];
    __shared__ float st[ROWS * STRIDE];

    const int band  = blockIdx.x;           // 0..15
    const int slice = blockIdx.y;           // 0..511
    const int tid   = threadIdx.x;          // 0..255
    const int gy0   = band * RB;
    const size_t base = (size_t)slice * (HW * HW);
    const float4* __restrict__ p4 = (const float4*)(pred + base);
    const float4* __restrict__ t4 = (const float4*)(targ + base);

    // Zero halo columns (col 0 and col 257) of every shared row.
    if (tid < ROWS) {
        sp[tid * STRIDE]       = 0.0f;
        sp[tid * STRIDE + 257] = 0.0f;
        st[tid * STRIDE]       = 0.0f;
        st[tid * STRIDE + 257] = 0.0f;
    }

    // Burst-load 18 rows x 64 float4 per array (coalesced; OOB rows -> zeros).
    // 1152 float4 per array / 256 threads = 4.5 -> 5 unrolled iterations,
    // all loads independent => deep MLP.
    #pragma unroll
    for (int i = tid; i < ROWS * 64; i += 256) {
        const int r  = i >> 6;              // shared row 0..17
        const int c  = i & 63;              // float4 col 0..63
        const int gy = gy0 - 1 + r;
        float4 pv = make_float4(0.f, 0.f, 0.f, 0.f);
        float4 tv = make_float4(0.f, 0.f, 0.f, 0.f);
        if ((unsigned)gy < (unsigned)HW) {
            pv = __ldg(p4 + gy * 64 + c);
            tv = __ldg(t4 + gy * 64 + c);
        }
        float* dp = sp + r * STRIDE + 1 + c * 4;
        dp[0] = pv.x; dp[1] = pv.y; dp[2] = pv.z; dp[3] = pv.w;
        float* dt = st + r * STRIDE + 1 + c * 4;
        dt[0] = tv.x; dt[1] = tv.y; dt[2] = tv.z; dt[3] = tv.w;
    }
    __syncthreads();

    // Each thread owns one column x, rolls down 16 output rows.
    const float* pc = sp + 1 + tid;         // center of column x, row 0
    const float* tc = st + 1 + tid;

    float pa2, pa1, pb2, pb1, ta2, ta1, tb2, tb1;
    horiz(pc,              pa2, pb2);
    horiz(pc + STRIDE,     pa1, pb1);
    horiz(tc,              ta2, tb2);
    horiz(tc + STRIDE,     ta1, tb1);

    float sum = 0.0f;
    #pragma unroll
    for (int y = 0; y < RB; y++) {
        float pa0, pb0, ta0, tb0;
        horiz(pc + (y + 2) * STRIDE, pa0, pb0);
        horiz(tc + (y + 2) * STRIDE, ta0, tb0);

        const float ex = fmaf(2.0f, pa1, pa2 + pa0);
        const float ey = pb0 - pb2;
        const float m2 = fmaf(ex, ex, fmaf(ey, ey, 1e-8f));
        const float mp = m2 * rsqrtf(m2);

        const float fx = fmaf(2.0f, ta1, ta2 + ta0);
        const float fy = tb0 - tb2;
        const float n2 = fmaf(fx, fx, fmaf(fy, fy, 1e-8f));
        const float mt = n2 * rsqrtf(n2);

        sum += fabsf(mp - mt);

        pa2 = pa1; pa1 = pa0; pb2 = pb1; pb1 = pb0;
        ta2 = ta1; ta1 = ta0; tb2 = tb1; tb1 = tb0;
    }

    // Warp reduce.
    #pragma unroll
    for (int o = 16; o > 0; o >>= 1)
        sum += __shfl_xor_sync(0xffffffffu, sum, o);

    __shared__ float wsum[8];
    if ((tid & 31) == 0) wsum[tid >> 5] = sum;
    __syncthreads();

    if (tid == 0) {
        double s = 0.0;
        #pragma unroll
        for (int i = 0; i < 8; i++) s += (double)wsum[i];
        atomicAdd(&g_accum, s);
        __threadfence();
        const unsigned ticket = atomicAdd(&g_count, 1u);
        if (ticket == NBLOCKS - 1) {
            // Every other block ordered its g_accum add before its ticket
            // increment (fence), and our ticket read acquires them.
            const double total = *((volatile double*)&g_accum);
            out[0] = (float)(total / N_TOTAL);
            // Self-reset for the next (graph-replayed) call.
            g_accum = 0.0;
            g_count = 0u;
            __threadfence();
        }
    }
}

extern "C" void kernel_launch(void* const* d_in, const int* in_sizes, int n_in,
                              void* d_out, int out_size) {
    const float* pred = (const float*)d_in[0];
    const float* targ = (const float*)d_in[1];
    float* out = (float*)d_out;

    dim3 grid(NBANDS, NSLICES);   // 16 x 512 = 8192 blocks
    ea_kernel<<<grid, 256>>>(pred, targ, out);
}